// round 4
// baseline (speedup 1.0000x reference)
#include <cuda_runtime.h>
#include <cuda_bf16.h>
#include <mma.h>
using namespace nvcuda;

#define BB 16
#define TT 128
#define HH 512
#define VV 32000
#define GG 1536          // 3*H
#define MROWS (BB*TT)    // 2048
#define NBLK 128         // persistent GRU grid

// ---------------- scratch (device globals; no runtime allocation) ----------
__device__ float g_xp[TT * BB * GG];             // [t*B+b][3H] incl. b_ih  (12.6 MB)
__device__ float g_hbuf[2][BB * HH];             // double-buffered GRU state
__device__ __nv_bfloat16 g_hs[MROWS * HH];       // gru_out bf16, row = b*T+t (2 MB)
__device__ __nv_bfloat16 g_wout[VV * HH];        // bf16 w_out (32.8 MB)
__device__ unsigned g_cnt;                       // zero-init
__device__ volatile unsigned g_gen;              // zero-init

// ---------------- grid-wide barrier (all CTAs resident) --------------------
__device__ __forceinline__ void grid_bar() {
    __threadfence();
    __syncthreads();
    if (threadIdx.x == 0) {
        unsigned gen = g_gen;
        if (atomicAdd(&g_cnt, 1u) == NBLK - 1u) {
            g_cnt = 0u;
            __threadfence();
            g_gen = gen + 1u;
        } else {
            while (g_gen == gen) { __nanosleep(64); }
        }
    }
    __syncthreads();
}

// ---------------- K0: w_out -> bf16 ---------------------------------------
__global__ void __launch_bounds__(256) k_convert(const float* __restrict__ w) {
    const int n4 = VV * HH / 4;
    for (int i = blockIdx.x * blockDim.x + threadIdx.x; i < n4;
         i += gridDim.x * blockDim.x) {
        float4 v = ((const float4*)w)[i];
        ((__nv_bfloat162*)g_wout)[2 * i + 0] = __floats2bfloat162_rn(v.x, v.y);
        ((__nv_bfloat162*)g_wout)[2 * i + 1] = __floats2bfloat162_rn(v.z, v.w);
    }
}

// ---------------- K1: x_proj = relu(emb[tok]) @ w_ih^T + b_ih --------------
// M=2048 (row = t*16+b), N=1536, K=512. 128x128 tile, BK=8, 8x8 microtile.
__global__ void __launch_bounds__(256) k_xproj(const float* __restrict__ emb,
                                               const int* __restrict__ tgt,
                                               const float* __restrict__ w_ih,
                                               const float* __restrict__ b_ih) {
    __shared__ float As[8][128];
    __shared__ float Bs[8][128];
    __shared__ int toks[128];
    const int tid = threadIdx.x;
    const int m0 = blockIdx.y * 128, n0 = blockIdx.x * 128;

    if (tid < 128) {
        int m = m0 + tid;
        int t = m >> 4, b = m & 15;
        toks[tid] = (t == 0) ? 1 : tgt[b * TT + t - 1];  // BOS = 1
    }
    __syncthreads();

    const int ra = tid >> 1, kc = (tid & 1) * 4;
    const float* arow = emb + (size_t)toks[ra] * HH;
    const float* brow = w_ih + (size_t)(n0 + ra) * HH;
    const int tx = tid & 15, ty = tid >> 4;

    float acc[8][8] = {};
    for (int k0 = 0; k0 < HH; k0 += 8) {
        float4 av = *(const float4*)(arow + k0 + kc);
        float4 bv = *(const float4*)(brow + k0 + kc);
        av.x = fmaxf(av.x, 0.f); av.y = fmaxf(av.y, 0.f);
        av.z = fmaxf(av.z, 0.f); av.w = fmaxf(av.w, 0.f);
        __syncthreads();
        As[kc + 0][ra] = av.x; As[kc + 1][ra] = av.y;
        As[kc + 2][ra] = av.z; As[kc + 3][ra] = av.w;
        Bs[kc + 0][ra] = bv.x; Bs[kc + 1][ra] = bv.y;
        Bs[kc + 2][ra] = bv.z; Bs[kc + 3][ra] = bv.w;
        __syncthreads();
#pragma unroll
        for (int k = 0; k < 8; k++) {
            float4 a0 = *(float4*)&As[k][ty * 8];
            float4 a1 = *(float4*)&As[k][ty * 8 + 4];
            float4 b0 = *(float4*)&Bs[k][tx * 8];
            float4 b1 = *(float4*)&Bs[k][tx * 8 + 4];
            float xv[8] = {a0.x, a0.y, a0.z, a0.w, a1.x, a1.y, a1.z, a1.w};
            float yv[8] = {b0.x, b0.y, b0.z, b0.w, b1.x, b1.y, b1.z, b1.w};
#pragma unroll
            for (int i = 0; i < 8; i++)
#pragma unroll
                for (int j = 0; j < 8; j++) acc[i][j] += xv[i] * yv[j];
        }
    }
    const float4 bi0 = *(const float4*)&b_ih[n0 + tx * 8];
    const float4 bi1 = *(const float4*)&b_ih[n0 + tx * 8 + 4];
#pragma unroll
    for (int i = 0; i < 8; i++) {
        float* orow = g_xp + (size_t)(m0 + ty * 8 + i) * GG + n0 + tx * 8;
        float4 o0, o1;
        o0.x = acc[i][0] + bi0.x; o0.y = acc[i][1] + bi0.y;
        o0.z = acc[i][2] + bi0.z; o0.w = acc[i][3] + bi0.w;
        o1.x = acc[i][4] + bi1.x; o1.y = acc[i][5] + bi1.y;
        o1.z = acc[i][6] + bi1.z; o1.w = acc[i][7] + bi1.w;
        *(float4*)orow = o0;
        *(float4*)(orow + 4) = o1;
    }
}

// ---------------- K2: persistent GRU scan ----------------------------------
// 128 blocks x 256 threads (8 warps). Warp pair (2 warps) owns one j in
// [0,512); each warp of the pair handles 8 of the 16 batch rows. w_hh rows
// for {j, j+512, j+1024} live in registers for the whole 128-step scan.
__global__ void __launch_bounds__(256) k_gru(const float* __restrict__ eh,
                                             const float* __restrict__ w_hh,
                                             const float* __restrict__ b_hh,
                                             float* __restrict__ out) {
    __shared__ float hsm[BB * HH];  // 32 KB
    const int tid = threadIdx.x;
    const int lane = tid & 31, warp = tid >> 5;
    const int j = (blockIdx.x << 2) + (warp >> 1);
    const int bbase = (warp & 1) * 8;

    float wr[16], wz[16], wn[16];
    {
        const float* p0 = w_hh + (size_t)j * HH;
        const float* p1 = w_hh + (size_t)(j + 512) * HH;
        const float* p2 = w_hh + (size_t)(j + 1024) * HH;
#pragma unroll
        for (int m = 0; m < 16; m++) {
            wr[m] = p0[lane + 32 * m];
            wz[m] = p1[lane + 32 * m];
            wn[m] = p2[lane + 32 * m];
        }
    }
    const float bhr = b_hh[j], bhz = b_hh[j + 512], bhn = b_hh[j + 1024];

    for (int i = tid; i < BB * HH; i += 256) hsm[i] = eh[i];
    __syncthreads();

    for (int t = 0; t < TT; t++) {
        float myh = 0.f;
        const float* xpt = g_xp + (size_t)t * BB * GG;
#pragma unroll
        for (int q = 0; q < 8; q++) {
            const int b = bbase + q;
            const float* hb = hsm + b * HH;
            float ar = 0.f, az = 0.f, an = 0.f;
#pragma unroll
            for (int m = 0; m < 16; m++) {
                float hv = hb[lane + 32 * m];
                ar += hv * wr[m]; az += hv * wz[m]; an += hv * wn[m];
            }
#pragma unroll
            for (int off = 16; off; off >>= 1) {
                ar += __shfl_xor_sync(0xFFFFFFFFu, ar, off);
                az += __shfl_xor_sync(0xFFFFFFFFu, az, off);
                an += __shfl_xor_sync(0xFFFFFFFFu, an, off);
            }
            const float* xpb = xpt + (size_t)b * GG;
            float r = 1.f / (1.f + __expf(-(xpb[j] + ar + bhr)));
            float z = 1.f / (1.f + __expf(-(xpb[j + 512] + az + bhz)));
            float n = tanhf(xpb[j + 1024] + r * (an + bhn));
            float hnew = (1.f - z) * n + z * hb[j];
            if (lane == q) myh = hnew;
        }
        const int nb = (t + 1) & 1;
        if (lane < 8) {
            const int b = bbase + lane;
            g_hbuf[nb][b * HH + j] = myh;
            g_hs[((size_t)b * TT + t) * HH + j] = __float2bfloat16(myh);
        }
        grid_bar();
        for (int i = tid; i < BB * HH; i += 256) hsm[i] = __ldcg(&g_hbuf[nb][i]);
        __syncthreads();
    }
    // hidden output (fp32) appended after log_probs
    if (blockIdx.x == 0) {
        for (int i = tid; i < BB * HH; i += 256)
            out[(size_t)MROWS * VV + i] = __ldcg(&g_hbuf[0][i]);
    }
}

// ---------------- K3: logits = gru_out @ w_out^T (bf16 WMMA, f32 acc) ------
// Writes raw logits DIRECTLY into d_out (in-place log-softmax follows).
// M=2048 (row = b*T+t), N=32000, K=512. 128x128x32 tiles, 8 warps (2x4),
// warp tile 64x32 = 4x2 m16n16k16 frags.
#define LG_LD 48
__global__ void __launch_bounds__(256) k_logits(float* __restrict__ out) {
    __shared__ __nv_bfloat16 As[128 * LG_LD];
    __shared__ __nv_bfloat16 Bs[128 * LG_LD];
    const int tid = threadIdx.x, warp = tid >> 5;
    const int wm = warp >> 2, wn = warp & 3;
    const int m0 = blockIdx.y * 128;
    const int n0 = blockIdx.x * 128;

    wmma::fragment<wmma::accumulator, 16, 16, 16, float> acc[4][2];
#pragma unroll
    for (int i = 0; i < 4; i++)
#pragma unroll
        for (int jj = 0; jj < 2; jj++) wmma::fill_fragment(acc[i][jj], 0.f);

    for (int k0 = 0; k0 < HH; k0 += 32) {
#pragma unroll
        for (int idx = tid; idx < 512; idx += 256) {
            const int r = idx >> 2, c = (idx & 3) * 8;
            *(uint4*)&As[r * LG_LD + c] =
                *(const uint4*)&g_hs[(size_t)(m0 + r) * HH + k0 + c];
            *(uint4*)&Bs[r * LG_LD + c] =
                *(const uint4*)&g_wout[(size_t)(n0 + r) * HH + k0 + c];
        }
        __syncthreads();
#pragma unroll
        for (int kk = 0; kk < 32; kk += 16) {
            wmma::fragment<wmma::matrix_a, 16, 16, 16, __nv_bfloat16,
                           wmma::row_major> af[4];
            wmma::fragment<wmma::matrix_b, 16, 16, 16, __nv_bfloat16,
                           wmma::col_major> bf[2];
#pragma unroll
            for (int i = 0; i < 4; i++)
                wmma::load_matrix_sync(af[i], &As[(wm * 64 + i * 16) * LG_LD + kk], LG_LD);
#pragma unroll
            for (int jj = 0; jj < 2; jj++)
                wmma::load_matrix_sync(bf[jj], &Bs[(wn * 32 + jj * 16) * LG_LD + kk], LG_LD);
#pragma unroll
            for (int i = 0; i < 4; i++)
#pragma unroll
                for (int jj = 0; jj < 2; jj++)
                    wmma::mma_sync(acc[i][jj], af[i], bf[jj], acc[i][jj]);
        }
        __syncthreads();
    }
#pragma unroll
    for (int i = 0; i < 4; i++)
#pragma unroll
        for (int jj = 0; jj < 2; jj++)
            wmma::store_matrix_sync(
                &out[(size_t)(m0 + wm * 64 + i * 16) * VV + n0 + wn * 32 + jj * 16],
                acc[i][jj], VV, wmma::mem_row_major);
}

// ---------------- K4: in-place log_softmax (bias folded here) --------------
__global__ void __launch_bounds__(256) k_lsm(const float* __restrict__ b_out,
                                             float* __restrict__ out) {
    __shared__ float sm[256], ss[256];
    const int tid = threadIdx.x;
    const size_t row = blockIdx.x;
    float* lg = out + row * VV;

    float m = -1e30f, s = 0.f;
    for (int i = tid; i < VV; i += 256) {
        float x = lg[i] + b_out[i];
        if (x > m) { s = s * __expf(m - x) + 1.f; m = x; }
        else s += __expf(x - m);
    }
    sm[tid] = m; ss[tid] = s;
    __syncthreads();
    for (int off = 128; off; off >>= 1) {
        if (tid < off) {
            float m2 = sm[tid + off], s2 = ss[tid + off];
            float M = fmaxf(sm[tid], m2);
            ss[tid] = ss[tid] * __expf(sm[tid] - M) + s2 * __expf(m2 - M);
            sm[tid] = M;
        }
        __syncthreads();
    }
    const float lse = sm[0] + logf(ss[0]);
    for (int i = tid; i < VV; i += 256) lg[i] = lg[i] + b_out[i] - lse;
}

// ---------------- launch ---------------------------------------------------
extern "C" void kernel_launch(void* const* d_in, const int* in_sizes, int n_in,
                              void* d_out, int out_size) {
    const float* enc_hidden = (const float*)d_in[1];
    const int*   tgt        = (const int*)d_in[2];
    const float* emb        = (const float*)d_in[3];
    const float* w_ih       = (const float*)d_in[4];
    const float* b_ih       = (const float*)d_in[5];
    const float* w_hh       = (const float*)d_in[6];
    const float* b_hh       = (const float*)d_in[7];
    const float* w_out      = (const float*)d_in[8];
    const float* b_out      = (const float*)d_in[9];
    float* out = (float*)d_out;

    k_convert<<<1024, 256>>>(w_out);

    dim3 gx(GG / 128, MROWS / 128);     // (12, 16)
    k_xproj<<<gx, 256>>>(emb, tgt, w_ih, b_ih);

    k_gru<<<NBLK, 256>>>(enc_hidden, w_hh, b_hh, out);

    dim3 gl(VV / 128, MROWS / 128);     // (250, 16)
    k_logits<<<gl, 256>>>(out);

    k_lsm<<<MROWS, 256>>>(b_out, out);
}